// round 8
// baseline (speedup 1.0000x reference)
#include <cuda_runtime.h>
#include <cuda_bf16.h>
#include <math.h>

#define T 1024
#define H 2048
#define I_DIM 1024
#define E 32
#define BM 64
#define BK 32

// smem layout (bytes, per kernel):
// stage unit (x3): A_hi 0..5120 | A_lo 5120..10240 | B raw fp32 10240..28672
//   gateup B raw: G 64x144 @10240, U 64x144 @19456
//   down   B raw: B 128x144 @10240
// bf16 B buffer (single): gateup GH 86016, GL 91136, UH 96256, UL 101376
//                         down   BH 86016, BL 96256
// spair @106496
#define STAGE_UNIT 28672
#define OFF_ALO    5120
#define OFF_B      10240
#define OFF_U      19456
#define OFF_BBUF   86016
#define OFF_SPAIR  106496
#define DYN_SMEM   106752

// Scratch (__device__ globals; no allocations allowed)
__device__ int   g_count[E];
__device__ int   g_list[E * 2 * T];
__device__ float g_pairw[T * 2];
__device__ __align__(16) unsigned g_xh[T * H / 2];         // x split hi (bf16x2)
__device__ __align__(16) unsigned g_xl[T * H / 2];         // x split lo
__device__ __align__(16) unsigned g_hh[T * 2 * I_DIM / 2]; // h split hi
__device__ __align__(16) unsigned g_hl[T * 2 * I_DIM / 2]; // h split lo

// ---------------------------------------------------------------------------
__global__ void zero_kernel(float* __restrict__ out) {
    int i = blockIdx.x * blockDim.x + threadIdx.x;
    if (i < T * H) out[i] = 0.0f;
    if (i < E) g_count[i] = 0;
}

__device__ __forceinline__ void split2(float2 v, unsigned &hi, unsigned &lo) {
    __nv_bfloat162 hb = __float22bfloat162_rn(v);
    float2 hf = __bfloat1622float2(hb);
    __nv_bfloat162 lb = __float22bfloat162_rn(make_float2(v.x - hf.x, v.y - hf.y));
    hi = *reinterpret_cast<unsigned*>(&hb);
    lo = *reinterpret_cast<unsigned*>(&lb);
}

__global__ void convert_x_kernel(const float* __restrict__ x) {
    int i = blockIdx.x * blockDim.x + threadIdx.x;
    float2 v = ((const float2*)x)[i];
    unsigned h, l;
    split2(v, h, l);
    g_xh[i] = h;
    g_xl[i] = l;
}

// ---------------------------------------------------------------------------
__global__ __launch_bounds__(128) void router_kernel(
    const float* __restrict__ x, const float* __restrict__ gw) {
    int t = blockIdx.x;
    __shared__ float logits[E];
    int warp = threadIdx.x >> 5;
    int lane = threadIdx.x & 31;
    const float4* xt = (const float4*)(x + (size_t)t * H);

    for (int e = warp; e < E; e += 4) {
        const float4* w = (const float4*)(gw + (size_t)e * H);
        float s = 0.0f;
        #pragma unroll 4
        for (int h = lane; h < H / 4; h += 32) {
            float4 a = xt[h];
            float4 b = w[h];
            s += a.x * b.x + a.y * b.y + a.z * b.z + a.w * b.w;
        }
        #pragma unroll
        for (int o = 16; o; o >>= 1) s += __shfl_xor_sync(0xffffffffu, s, o);
        if (lane == 0) logits[e] = s;
    }
    __syncthreads();

    if (threadIdx.x == 0) {
        float b1 = -1e30f, b2 = -1e30f;
        int i1 = 0, i2 = 0;
        #pragma unroll
        for (int e = 0; e < E; e++) {
            float v = logits[e];
            if (v > b1)      { b2 = b1; i2 = i1; b1 = v; i1 = e; }
            else if (v > b2) { b2 = v; i2 = e; }
        }
        float w1 = 1.0f / (1.0f + expf(b2 - b1));
        float w2 = 1.0f - w1;
        g_pairw[t * 2 + 0] = w1;
        g_pairw[t * 2 + 1] = w2;
        int p1 = atomicAdd(&g_count[i1], 1);
        g_list[i1 * 2 * T + p1] = t * 2 + 0;
        int p2 = atomicAdd(&g_count[i2], 1);
        g_list[i2 * 2 * T + p2] = t * 2 + 1;
    }
}

// ---------------------------------------------------------------------------
__device__ __forceinline__ unsigned smem_u32(const void* p) {
    return (unsigned)__cvta_generic_to_shared(p);
}
__device__ __forceinline__ void ldsm_x4(unsigned addr, unsigned (&r)[4]) {
    asm volatile("ldmatrix.sync.aligned.m8n8.x4.shared.b16 {%0,%1,%2,%3}, [%4];\n"
        : "=r"(r[0]), "=r"(r[1]), "=r"(r[2]), "=r"(r[3]) : "r"(addr));
}
__device__ __forceinline__ void mma16816(float (&c)[4], const unsigned (&a)[4],
                                         unsigned b0, unsigned b1) {
    asm volatile(
        "mma.sync.aligned.m16n8k16.row.col.f32.bf16.bf16.f32 "
        "{%0,%1,%2,%3}, {%4,%5,%6,%7}, {%8,%9}, {%0,%1,%2,%3};\n"
        : "+f"(c[0]), "+f"(c[1]), "+f"(c[2]), "+f"(c[3])
        : "r"(a[0]), "r"(a[1]), "r"(a[2]), "r"(a[3]), "r"(b0), "r"(b1));
}
__device__ __forceinline__ void cp_async16(unsigned dst, const void* src) {
    asm volatile("cp.async.cg.shared.global [%0], [%1], 16;\n" :: "r"(dst), "l"(src));
}
#define CP_COMMIT() asm volatile("cp.async.commit_group;\n" ::: "memory")
#define CP_WAIT(n)  asm volatile("cp.async.wait_group %0;\n" :: "n"(n) : "memory")

// ---------------------------------------------------------------------------
// Gate+Up: M=64 slots x N=64 i-cols, K=H. 3-stage cp.async pipeline.
__global__ __launch_bounds__(256) void gateup_kernel(
    const float* __restrict__ Wg, const float* __restrict__ Wu) {
    extern __shared__ char ds[];
    int e = blockIdx.z;
    int cnt = g_count[e];
    int slot0 = blockIdx.x * BM;
    if (slot0 >= cnt) return;
    int i0 = blockIdx.y * 64;

    int tid = threadIdx.x;
    int* spair = (int*)(ds + OFF_SPAIR);
    if (tid < BM) {
        int s = slot0 + tid;
        spair[tid] = (s < cnt) ? g_list[e * 2 * T + s] : g_list[e * 2 * T];
    }
    __syncthreads();

    unsigned sbase = smem_u32(ds);
    int arow = tid >> 2;          // 0..63
    int achk = tid & 3;           // 16B chunk id
    int token = spair[arow] >> 1;
    const char* srcAh = (const char*)g_xh + (size_t)token * H * 2 + achk * 16;
    const char* srcAl = (const char*)g_xl + (size_t)token * H * 2 + achk * 16;
    const char* srcG = (const char*)(Wg + ((size_t)e * I_DIM + i0 + arow) * H) + achk * 16;
    const char* srcU = (const char*)(Wu + ((size_t)e * I_DIM + i0 + arow) * H) + achk * 16;
    unsigned dstA = arow * 80 + achk * 16;      // A pitch 40 bf16 = 80B
    unsigned dstB = arow * 144 + achk * 16;     // B raw pitch 36 fp32 = 144B

    int warp = tid >> 5, lane = tid & 31;
    int wm = warp >> 2;   // 0..1 (32 rows)
    int wn = warp & 3;    // 0..3 (16 cols)

    unsigned aoff0 = ((wm * 32 + (lane & 15)) * 40 + (lane >> 4) * 8) * 2;
    unsigned aoff1 = aoff0 + 16 * 80;
    unsigned boff  = ((wn * 16 + (lane & 7) + ((lane >> 4) & 1) * 8) * 40
                      + ((lane >> 3) & 1) * 8) * 2;

    float cg[2][2][4] = {};
    float cu[2][2][4] = {};

    auto stage_load = [&](int s) {
        unsigned sb = sbase + (s % 3) * STAGE_UNIT;
        size_t kA = (size_t)s * 64;    // BK*2 bytes of bf16
        size_t kB = (size_t)s * 128;   // BK*4 bytes of fp32
        cp_async16(sb + dstA, srcAh + kA);
        cp_async16(sb + OFF_ALO + dstA, srcAl + kA);
        cp_async16(sb + OFF_B + dstB, srcG + kB);
        cp_async16(sb + OFF_B + dstB + 64, srcG + kB + 64);
        cp_async16(sb + OFF_U + dstB, srcU + kB);
        cp_async16(sb + OFF_U + dstB + 64, srcU + kB + 64);
        CP_COMMIT();
    };

    unsigned* GH = (unsigned*)(ds + OFF_BBUF);
    unsigned* GL = (unsigned*)(ds + OFF_BBUF + 5120);
    unsigned* UH = (unsigned*)(ds + OFF_BBUF + 10240);
    unsigned* UL = (unsigned*)(ds + OFF_BBUF + 15360);

    stage_load(0);
    stage_load(1);

    const int NIT = H / BK;   // 64
    for (int t = 0; t < NIT; t++) {
        __syncthreads();                       // prior MMA done with stage (t+2)%3 and Bbuf
        if (t + 2 < NIT) { stage_load(t + 2); CP_WAIT(2); }
        else if (t + 1 < NIT) { CP_WAIT(1); }
        else { CP_WAIT(0); }

        // convert: thread-local (reads exactly what this thread staged)
        {
            const float* rG = (const float*)(ds + (t % 3) * STAGE_UNIT + OFF_B + arow * 144);
            const float* rU = (const float*)(ds + (t % 3) * STAGE_UNIT + OFF_U + arow * 144);
            #pragma unroll
            for (int gsel = 0; gsel < 2; gsel++) {
                int offs = achk * 4 + gsel * 16;
                int widx = arow * 20 + (offs >> 1);
                float2 v0 = *(const float2*)(rG + offs);
                float2 v1 = *(const float2*)(rG + offs + 2);
                unsigned h0, l0, h1, l1;
                split2(v0, h0, l0); split2(v1, h1, l1);
                GH[widx] = h0; GH[widx + 1] = h1;
                GL[widx] = l0; GL[widx + 1] = l1;
                float2 w0 = *(const float2*)(rU + offs);
                float2 w1 = *(const float2*)(rU + offs + 2);
                split2(w0, h0, l0); split2(w1, h1, l1);
                UH[widx] = h0; UH[widx + 1] = h1;
                UL[widx] = l0; UL[widx + 1] = l1;
            }
        }
        __syncthreads();                       // Bbuf + A stage visible

        unsigned st = sbase + (t % 3) * STAGE_UNIT;
        #pragma unroll
        for (int ks = 0; ks < 2; ks++) {
            unsigned kb = ks * 32;
            unsigned ah0[4], ah1[4], al0[4], al1[4];
            ldsm_x4(st + aoff0 + kb, ah0);
            ldsm_x4(st + aoff1 + kb, ah1);
            ldsm_x4(st + OFF_ALO + aoff0 + kb, al0);
            ldsm_x4(st + OFF_ALO + aoff1 + kb, al1);
            unsigned bgh[4], bgl[4], buh[4], bul[4];
            ldsm_x4(sbase + OFF_BBUF + boff + kb, bgh);
            ldsm_x4(sbase + OFF_BBUF + 5120 + boff + kb, bgl);
            ldsm_x4(sbase + OFF_BBUF + 10240 + boff + kb, buh);
            ldsm_x4(sbase + OFF_BBUF + 15360 + boff + kb, bul);

            mma16816(cg[0][0], ah0, bgh[0], bgh[1]);
            mma16816(cg[0][0], ah0, bgl[0], bgl[1]);
            mma16816(cg[0][0], al0, bgh[0], bgh[1]);
            mma16816(cg[0][1], ah0, bgh[2], bgh[3]);
            mma16816(cg[0][1], ah0, bgl[2], bgl[3]);
            mma16816(cg[0][1], al0, bgh[2], bgh[3]);
            mma16816(cg[1][0], ah1, bgh[0], bgh[1]);
            mma16816(cg[1][0], ah1, bgl[0], bgl[1]);
            mma16816(cg[1][0], al1, bgh[0], bgh[1]);
            mma16816(cg[1][1], ah1, bgh[2], bgh[3]);
            mma16816(cg[1][1], ah1, bgl[2], bgl[3]);
            mma16816(cg[1][1], al1, bgh[2], bgh[3]);

            mma16816(cu[0][0], ah0, buh[0], buh[1]);
            mma16816(cu[0][0], ah0, bul[0], bul[1]);
            mma16816(cu[0][0], al0, buh[0], buh[1]);
            mma16816(cu[0][1], ah0, buh[2], buh[3]);
            mma16816(cu[0][1], ah0, bul[2], bul[3]);
            mma16816(cu[0][1], al0, buh[2], buh[3]);
            mma16816(cu[1][0], ah1, buh[0], buh[1]);
            mma16816(cu[1][0], ah1, bul[0], bul[1]);
            mma16816(cu[1][0], al1, buh[0], buh[1]);
            mma16816(cu[1][1], ah1, buh[2], buh[3]);
            mma16816(cu[1][1], ah1, bul[2], bul[3]);
            mma16816(cu[1][1], al1, buh[2], buh[3]);
        }
    }

    // epilogue: h = silu(g)*u*w -> bf16 hi/lo to g_hh/g_hl
    #pragma unroll
    for (int mi = 0; mi < 2; mi++) {
        #pragma unroll
        for (int half = 0; half < 2; half++) {
            int row = wm * 32 + mi * 16 + (lane >> 2) + half * 8;
            if (slot0 + row < cnt) {
                int pair = spair[row];
                float w = g_pairw[pair];
                #pragma unroll
                for (int ni = 0; ni < 2; ni++) {
                    int col = i0 + wn * 16 + ni * 8 + ((lane & 3) << 1);
                    float g0 = cg[mi][ni][half * 2 + 0];
                    float g1 = cg[mi][ni][half * 2 + 1];
                    float u0 = cu[mi][ni][half * 2 + 0];
                    float u1 = cu[mi][ni][half * 2 + 1];
                    float h0 = g0 / (1.0f + expf(-g0)) * u0 * w;
                    float h1 = g1 / (1.0f + expf(-g1)) * u1 * w;
                    unsigned hv, lv;
                    split2(make_float2(h0, h1), hv, lv);
                    size_t idx = ((size_t)pair * I_DIM + col) >> 1;
                    g_hh[idx] = hv;
                    g_hl[idx] = lv;
                }
            }
        }
    }
}

// ---------------------------------------------------------------------------
// Down: M=64 slots x N=128 h-cols, K=I. Same 3-stage pipeline.
__global__ __launch_bounds__(256) void down_kernel(
    const float* __restrict__ Wd, float* __restrict__ out) {
    extern __shared__ char ds[];
    int e = blockIdx.z;
    int cnt = g_count[e];
    int slot0 = blockIdx.x * BM;
    if (slot0 >= cnt) return;
    int h0 = blockIdx.y * 128;

    int tid = threadIdx.x;
    int* spair = (int*)(ds + OFF_SPAIR);
    if (tid < BM) {
        int s = slot0 + tid;
        spair[tid] = (s < cnt) ? g_list[e * 2 * T + s] : g_list[e * 2 * T];
    }
    __syncthreads();

    unsigned sbase = smem_u32(ds);
    int arow = tid >> 2;
    int achk = tid & 3;
    int pr = spair[arow];
    const char* srcAh = (const char*)g_hh + (size_t)pr * I_DIM * 2 + achk * 16;
    const char* srcAl = (const char*)g_hl + (size_t)pr * I_DIM * 2 + achk * 16;
    unsigned dstA = arow * 80 + achk * 16;
    int brow = tid >> 1;          // 0..127
    int bhalf = tid & 1;
    const char* srcB = (const char*)(Wd + ((size_t)e * H + h0 + brow) * I_DIM) + bhalf * 64;
    unsigned dstB = brow * 144 + bhalf * 64;

    int warp = tid >> 5, lane = tid & 31;
    int wm = warp >> 2;
    int wn = warp & 3;

    unsigned aoff0 = ((wm * 32 + (lane & 15)) * 40 + (lane >> 4) * 8) * 2;
    unsigned aoff1 = aoff0 + 16 * 80;
    unsigned boffbase = ((wn * 32 + (lane & 7) + ((lane >> 4) & 1) * 8) * 40
                         + ((lane >> 3) & 1) * 8) * 2;

    float c[2][4][4] = {};

    auto stage_load = [&](int s) {
        unsigned sb = sbase + (s % 3) * STAGE_UNIT;
        size_t kA = (size_t)s * 64;
        size_t kB = (size_t)s * 128;
        cp_async16(sb + dstA, srcAh + kA);
        cp_async16(sb + OFF_ALO + dstA, srcAl + kA);
        cp_async16(sb + OFF_B + dstB, srcB + kB);
        cp_async16(sb + OFF_B + dstB + 16, srcB + kB + 16);
        cp_async16(sb + OFF_B + dstB + 32, srcB + kB + 32);
        cp_async16(sb + OFF_B + dstB + 48, srcB + kB + 48);
        CP_COMMIT();
    };

    unsigned* BH = (unsigned*)(ds + OFF_BBUF);
    unsigned* BL = (unsigned*)(ds + OFF_BBUF + 10240);

    stage_load(0);
    stage_load(1);

    const int NIT = I_DIM / BK;   // 32
    for (int t = 0; t < NIT; t++) {
        __syncthreads();
        if (t + 2 < NIT) { stage_load(t + 2); CP_WAIT(2); }
        else if (t + 1 < NIT) { CP_WAIT(1); }
        else { CP_WAIT(0); }

        // convert own staged B floats -> bf16 hi/lo
        {
            const float* rB = (const float*)(ds + (t % 3) * STAGE_UNIT + OFF_B + brow * 144);
            #pragma unroll
            for (int j = 0; j < 4; j++) {
                int offs = bhalf * 16 + j * 4;
                int widx = brow * 20 + (offs >> 1);
                float2 v0 = *(const float2*)(rB + offs);
                float2 v1 = *(const float2*)(rB + offs + 2);
                unsigned h0, l0, h1, l1;
                split2(v0, h0, l0); split2(v1, h1, l1);
                BH[widx] = h0; BH[widx + 1] = h1;
                BL[widx] = l0; BL[widx + 1] = l1;
            }
        }
        __syncthreads();

        unsigned st = sbase + (t % 3) * STAGE_UNIT;
        #pragma unroll
        for (int ks = 0; ks < 2; ks++) {
            unsigned kb = ks * 32;
            unsigned ah0[4], ah1[4], al0[4], al1[4];
            ldsm_x4(st + aoff0 + kb, ah0);
            ldsm_x4(st + aoff1 + kb, ah1);
            ldsm_x4(st + OFF_ALO + aoff0 + kb, al0);
            ldsm_x4(st + OFF_ALO + aoff1 + kb, al1);
            unsigned bh0[4], bh1[4], bl0[4], bl1[4];
            ldsm_x4(sbase + OFF_BBUF + boffbase + kb, bh0);
            ldsm_x4(sbase + OFF_BBUF + boffbase + 1280 + kb, bh1);
            ldsm_x4(sbase + OFF_BBUF + 10240 + boffbase + kb, bl0);
            ldsm_x4(sbase + OFF_BBUF + 10240 + boffbase + 1280 + kb, bl1);

            #pragma unroll
            for (int mi = 0; mi < 2; mi++) {
                const unsigned (&ah)[4] = mi ? ah1 : ah0;
                const unsigned (&al)[4] = mi ? al1 : al0;
                mma16816(c[mi][0], ah, bh0[0], bh0[1]);
                mma16816(c[mi][0], ah, bl0[0], bl0[1]);
                mma16816(c[mi][0], al, bh0[0], bh0[1]);
                mma16816(c[mi][1], ah, bh0[2], bh0[3]);
                mma16816(c[mi][1], ah, bl0[2], bl0[3]);
                mma16816(c[mi][1], al, bh0[2], bh0[3]);
                mma16816(c[mi][2], ah, bh1[0], bh1[1]);
                mma16816(c[mi][2], ah, bl1[0], bl1[1]);
                mma16816(c[mi][2], al, bh1[0], bh1[1]);
                mma16816(c[mi][3], ah, bh1[2], bh1[3]);
                mma16816(c[mi][3], ah, bl1[2], bl1[3]);
                mma16816(c[mi][3], al, bh1[2], bh1[3]);
            }
        }
    }

    // epilogue: scatter-add into out[token][h]
    #pragma unroll
    for (int mi = 0; mi < 2; mi++) {
        #pragma unroll
        for (int half = 0; half < 2; half++) {
            int row = wm * 32 + mi * 16 + (lane >> 2) + half * 8;
            if (slot0 + row < cnt) {
                int token = spair[row] >> 1;
                float* orow = out + (size_t)token * H + h0 + wn * 32;
                #pragma unroll
                for (int ni = 0; ni < 4; ni++) {
                    int col = ni * 8 + ((lane & 3) << 1);
                    atomicAdd(&orow[col],     c[mi][ni][half * 2 + 0]);
                    atomicAdd(&orow[col + 1], c[mi][ni][half * 2 + 1]);
                }
            }
        }
    }
}

// ---------------------------------------------------------------------------
extern "C" void kernel_launch(void* const* d_in, const int* in_sizes, int n_in,
                              void* d_out, int out_size) {
    const float* x  = (const float*)d_in[0];
    const float* gw = (const float*)d_in[1];
    const float* Wg = (const float*)d_in[2];
    const float* Wu = (const float*)d_in[3];
    const float* Wd = (const float*)d_in[4];
    float* out = (float*)d_out;

    cudaFuncSetAttribute(gateup_kernel,
        cudaFuncAttributeMaxDynamicSharedMemorySize, DYN_SMEM);
    cudaFuncSetAttribute(down_kernel,
        cudaFuncAttributeMaxDynamicSharedMemorySize, DYN_SMEM);

    zero_kernel<<<(T * H + 255) / 256, 256>>>(out);
    convert_x_kernel<<<(T * H / 2) / 256, 256>>>(x);
    router_kernel<<<T, 128>>>(x, gw);
    {
        dim3 grid(T * 2 / BM, I_DIM / 64, E);
        gateup_kernel<<<grid, 256, DYN_SMEM>>>(Wg, Wu);
    }
    {
        dim3 grid(T * 2 / BM, H / 128, E);
        down_kernel<<<grid, 256, DYN_SMEM>>>(Wd, out);
    }
}

// round 10
// speedup vs baseline: 1.5838x; 1.5838x over previous
#include <cuda_runtime.h>
#include <cuda_fp16.h>
#include <math.h>

#define T 1024
#define H 2048
#define I_DIM 1024
#define E 32

#define BM 64
#define BK 32
#define PITCH 40   // fp16 elems per smem row: 32 + 8 pad -> conflict-free ldmatrix

// Scratch (no allocations allowed -> __device__ globals)
__device__ int   g_count[E];
__device__ int   g_list[E * 2 * T];      // pair ids (t*2+k) grouped per expert
__device__ float g_pairw[T * 2];         // combine weight per (token,k) pair
__device__ float g_hbuf[(size_t)T * 2 * I_DIM];  // silu(g)*u*w, 8 MB

// ---------------------------------------------------------------------------
__global__ void zero_kernel(float* __restrict__ out) {
    int i = blockIdx.x * blockDim.x + threadIdx.x;
    if (i < T * H) out[i] = 0.0f;
    if (i < E) g_count[i] = 0;
}

// ---------------------------------------------------------------------------
__global__ __launch_bounds__(128) void router_kernel(
    const float* __restrict__ x, const float* __restrict__ gw) {
    int t = blockIdx.x;
    __shared__ float logits[E];
    int warp = threadIdx.x >> 5;
    int lane = threadIdx.x & 31;
    const float4* xt = (const float4*)(x + (size_t)t * H);

    for (int e = warp; e < E; e += 4) {
        const float4* w = (const float4*)(gw + (size_t)e * H);
        float s = 0.0f;
        #pragma unroll 4
        for (int h = lane; h < H / 4; h += 32) {
            float4 a = xt[h];
            float4 b = w[h];
            s += a.x * b.x + a.y * b.y + a.z * b.z + a.w * b.w;
        }
        #pragma unroll
        for (int o = 16; o; o >>= 1) s += __shfl_xor_sync(0xffffffffu, s, o);
        if (lane == 0) logits[e] = s;
    }
    __syncthreads();

    if (threadIdx.x == 0) {
        float b1 = -1e30f, b2 = -1e30f;
        int i1 = 0, i2 = 0;
        #pragma unroll
        for (int e = 0; e < E; e++) {
            float v = logits[e];
            if (v > b1)      { b2 = b1; i2 = i1; b1 = v; i1 = e; }
            else if (v > b2) { b2 = v; i2 = e; }
        }
        float w1 = 1.0f / (1.0f + expf(b2 - b1));
        float w2 = 1.0f - w1;
        g_pairw[t * 2 + 0] = w1;
        g_pairw[t * 2 + 1] = w2;
        int p1 = atomicAdd(&g_count[i1], 1);
        g_list[i1 * 2 * T + p1] = t * 2 + 0;
        int p2 = atomicAdd(&g_count[i2], 1);
        g_list[i2 * 2 * T + p2] = t * 2 + 1;
    }
}

// ---------------------------------------------------------------------------
// MMA helpers
__device__ __forceinline__ unsigned smem_u32(const void* p) {
    return (unsigned)__cvta_generic_to_shared(p);
}

__device__ __forceinline__ void ldsm_x4(unsigned addr, unsigned (&r)[4]) {
    asm volatile("ldmatrix.sync.aligned.m8n8.x4.shared.b16 {%0,%1,%2,%3}, [%4];\n"
        : "=r"(r[0]), "=r"(r[1]), "=r"(r[2]), "=r"(r[3]) : "r"(addr));
}

__device__ __forceinline__ void mma16816(float (&c)[4], const unsigned (&a)[4],
                                         unsigned b0, unsigned b1) {
    asm volatile(
        "mma.sync.aligned.m16n8k16.row.col.f32.f16.f16.f32 "
        "{%0,%1,%2,%3}, {%4,%5,%6,%7}, {%8,%9}, {%0,%1,%2,%3};\n"
        : "+f"(c[0]), "+f"(c[1]), "+f"(c[2]), "+f"(c[3])
        : "r"(a[0]), "r"(a[1]), "r"(a[2]), "r"(a[3]), "r"(b0), "r"(b1));
}

// convert fp32x4 -> fp16x4 (two packed half2)
__device__ __forceinline__ uint2 cvt4(float4 v) {
    __half2 h0 = __float22half2_rn(make_float2(v.x, v.y));
    __half2 h1 = __float22half2_rn(make_float2(v.z, v.w));
    uint2 r;
    r.x = *reinterpret_cast<unsigned*>(&h0);
    r.y = *reinterpret_cast<unsigned*>(&h1);
    return r;
}

// ---------------------------------------------------------------------------
// Gate+Up: per-expert gathered GEMM, M=64 slots, N=64 i-cols (g AND u), K=H.
// Single-product fp16 mma.sync, fp32 accum. Reg-prefetch pipeline (R6).
#define BN_GU 64

__global__ __launch_bounds__(256) void gateup_kernel(
    const float* __restrict__ x,
    const float* __restrict__ Wg,
    const float* __restrict__ Wu) {
    int e = blockIdx.z;
    int cnt = g_count[e];
    int slot0 = blockIdx.x * BM;
    if (slot0 >= cnt) return;
    int i0 = blockIdx.y * BN_GU;

    __shared__ __align__(16) __half sA[BM * PITCH];
    __shared__ __align__(16) __half sG[BN_GU * PITCH];
    __shared__ __align__(16) __half sU[BN_GU * PITCH];
    __shared__ int spair[BM];

    int tid = threadIdx.x;
    if (tid < BM) {
        int s = slot0 + tid;
        spair[tid] = (s < cnt) ? g_list[e * 2 * T + s] : g_list[e * 2 * T];
    }
    __syncthreads();

    // global load mapping: 2 float4 per tile per thread
    int r1 = tid >> 3;            // 0..31
    int c4 = (tid & 7) << 2;      // 0,4,...,28
    int r2 = r1 + 32;
    const float* a1 = x + (size_t)(spair[r1] >> 1) * H + c4;
    const float* a2 = x + (size_t)(spair[r2] >> 1) * H + c4;
    const float* gp1 = Wg + ((size_t)e * I_DIM + i0 + r1) * H + c4;
    const float* gp2 = gp1 + (size_t)32 * H;
    const float* up1 = Wu + ((size_t)e * I_DIM + i0 + r1) * H + c4;
    const float* up2 = up1 + (size_t)32 * H;
    int off1 = r1 * PITCH + c4;
    int off2 = r2 * PITCH + c4;

    int warp = tid >> 5, lane = tid & 31;
    int wm = warp >> 2;           // 0..1  (32 rows each)
    int wn = warp & 3;            // 0..3  (16 cols each)

    unsigned uA = smem_u32(sA);
    unsigned uG = smem_u32(sG);
    unsigned uU = smem_u32(sU);

    unsigned aoff0 = ((wm * 32 + (lane & 15)) * PITCH + (lane >> 4) * 8) * 2;
    unsigned aoff1 = aoff0 + 16 * PITCH * 2;
    unsigned boff  = ((wn * 16 + (lane & 7) + ((lane >> 4) & 1) * 8) * PITCH
                      + ((lane >> 3) & 1) * 8) * 2;

    float cg[2][2][4] = {};
    float cu[2][2][4] = {};

    // prologue loads
    float4 va1 = *(const float4*)(a1);
    float4 va2 = *(const float4*)(a2);
    float4 vg1 = *(const float4*)(gp1);
    float4 vg2 = *(const float4*)(gp2);
    float4 vu1 = *(const float4*)(up1);
    float4 vu2 = *(const float4*)(up2);

    for (int k0 = 0; k0 < H; k0 += BK) {
        __syncthreads();
        *(uint2*)&sA[off1] = cvt4(va1);
        *(uint2*)&sA[off2] = cvt4(va2);
        *(uint2*)&sG[off1] = cvt4(vg1);
        *(uint2*)&sG[off2] = cvt4(vg2);
        *(uint2*)&sU[off1] = cvt4(vu1);
        *(uint2*)&sU[off2] = cvt4(vu2);
        __syncthreads();

        int kn = k0 + BK;
        if (kn < H) {   // prefetch next iteration; latency hides under MMA
            va1 = *(const float4*)(a1 + kn);
            va2 = *(const float4*)(a2 + kn);
            vg1 = *(const float4*)(gp1 + kn);
            vg2 = *(const float4*)(gp2 + kn);
            vu1 = *(const float4*)(up1 + kn);
            vu2 = *(const float4*)(up2 + kn);
        }

        #pragma unroll
        for (int ks = 0; ks < 2; ks++) {
            unsigned kb = ks * 32;   // 16 halves = 32 bytes
            unsigned ah0[4], ah1[4];
            ldsm_x4(uA + aoff0 + kb, ah0);
            ldsm_x4(uA + aoff1 + kb, ah1);
            unsigned bg[4], bu[4];
            ldsm_x4(uG + boff + kb, bg);
            ldsm_x4(uU + boff + kb, bu);

            mma16816(cg[0][0], ah0, bg[0], bg[1]);
            mma16816(cg[0][1], ah0, bg[2], bg[3]);
            mma16816(cg[1][0], ah1, bg[0], bg[1]);
            mma16816(cg[1][1], ah1, bg[2], bg[3]);
            mma16816(cu[0][0], ah0, bu[0], bu[1]);
            mma16816(cu[0][1], ah0, bu[2], bu[3]);
            mma16816(cu[1][0], ah1, bu[0], bu[1]);
            mma16816(cu[1][1], ah1, bu[2], bu[3]);
        }
    }

    // epilogue: h = silu(g) * u * combine_weight -> g_hbuf[pair][i]
    #pragma unroll
    for (int mi = 0; mi < 2; mi++) {
        #pragma unroll
        for (int half = 0; half < 2; half++) {
            int row = wm * 32 + mi * 16 + (lane >> 2) + half * 8;
            if (slot0 + row < cnt) {
                int pair = spair[row];
                float w = g_pairw[pair];
                float* hrow = g_hbuf + (size_t)pair * I_DIM + i0 + wn * 16;
                #pragma unroll
                for (int ni = 0; ni < 2; ni++) {
                    int col = ni * 8 + ((lane & 3) << 1);
                    float g0 = cg[mi][ni][half * 2 + 0];
                    float g1 = cg[mi][ni][half * 2 + 1];
                    float u0 = cu[mi][ni][half * 2 + 0];
                    float u1 = cu[mi][ni][half * 2 + 1];
                    hrow[col]     = g0 / (1.0f + expf(-g0)) * u0 * w;
                    hrow[col + 1] = g1 / (1.0f + expf(-g1)) * u1 * w;
                }
            }
        }
    }
}

// ---------------------------------------------------------------------------
// Down: per-expert gathered GEMM, M=64 slots, N=128 h-cols, K=I. Scatter-add.
#define BN_D 128

__global__ __launch_bounds__(256) void down_kernel(
    const float* __restrict__ Wd, float* __restrict__ out) {
    int e = blockIdx.z;
    int cnt = g_count[e];
    int slot0 = blockIdx.x * BM;
    if (slot0 >= cnt) return;
    int h0 = blockIdx.y * BN_D;

    __shared__ __align__(16) __half sA[BM * PITCH];
    __shared__ __align__(16) __half sB[BN_D * PITCH];
    __shared__ int spair[BM];

    int tid = threadIdx.x;
    if (tid < BM) {
        int s = slot0 + tid;
        spair[tid] = (s < cnt) ? g_list[e * 2 * T + s] : g_list[e * 2 * T];
    }
    __syncthreads();

    int r1 = tid >> 3;
    int c4 = (tid & 7) << 2;
    int r2 = r1 + 32;
    const float* a1 = g_hbuf + (size_t)spair[r1] * I_DIM + c4;
    const float* a2 = g_hbuf + (size_t)spair[r2] * I_DIM + c4;
    const float* b1 = Wd + ((size_t)e * H + h0 + r1) * I_DIM + c4;
    const float* b2 = b1 + (size_t)32 * I_DIM;
    const float* b3 = b1 + (size_t)64 * I_DIM;
    const float* b4 = b1 + (size_t)96 * I_DIM;
    int offA1 = r1 * PITCH + c4;
    int offA2 = r2 * PITCH + c4;

    int warp = tid >> 5, lane = tid & 31;
    int wm = warp >> 2;           // 0..1
    int wn = warp & 3;            // 0..3 (32 cols each)

    unsigned uA = smem_u32(sA);
    unsigned uB = smem_u32(sB);

    unsigned aoff0 = ((wm * 32 + (lane & 15)) * PITCH + (lane >> 4) * 8) * 2;
    unsigned aoff1 = aoff0 + 16 * PITCH * 2;
    unsigned boffbase = ((wn * 32 + (lane & 7) + ((lane >> 4) & 1) * 8) * PITCH
                         + ((lane >> 3) & 1) * 8) * 2;

    float c[2][4][4] = {};

    // prologue loads
    float4 va1 = *(const float4*)(a1);
    float4 va2 = *(const float4*)(a2);
    float4 vb1 = *(const float4*)(b1);
    float4 vb2 = *(const float4*)(b2);
    float4 vb3 = *(const float4*)(b3);
    float4 vb4 = *(const float4*)(b4);

    for (int k0 = 0; k0 < I_DIM; k0 += BK) {
        __syncthreads();
        *(uint2*)&sA[offA1] = cvt4(va1);
        *(uint2*)&sA[offA2] = cvt4(va2);
        *(uint2*)&sB[offA1] = cvt4(vb1);
        *(uint2*)&sB[offA2] = cvt4(vb2);
        *(uint2*)&sB[offA1 + 64 * PITCH] = cvt4(vb3);
        *(uint2*)&sB[offA2 + 64 * PITCH] = cvt4(vb4);
        __syncthreads();

        int kn = k0 + BK;
        if (kn < I_DIM) {
            va1 = *(const float4*)(a1 + kn);
            va2 = *(const float4*)(a2 + kn);
            vb1 = *(const float4*)(b1 + kn);
            vb2 = *(const float4*)(b2 + kn);
            vb3 = *(const float4*)(b3 + kn);
            vb4 = *(const float4*)(b4 + kn);
        }

        #pragma unroll
        for (int ks = 0; ks < 2; ks++) {
            unsigned kb = ks * 32;
            unsigned ah0[4], ah1[4];
            ldsm_x4(uA + aoff0 + kb, ah0);
            ldsm_x4(uA + aoff1 + kb, ah1);
            unsigned bh0[4], bh1[4];
            ldsm_x4(uB + boffbase + kb, bh0);
            ldsm_x4(uB + boffbase + 16 * PITCH * 2 + kb, bh1);

            #pragma unroll
            for (int mi = 0; mi < 2; mi++) {
                const unsigned (&ah)[4] = mi ? ah1 : ah0;
                mma16816(c[mi][0], ah, bh0[0], bh0[1]);
                mma16816(c[mi][1], ah, bh0[2], bh0[3]);
                mma16816(c[mi][2], ah, bh1[0], bh1[1]);
                mma16816(c[mi][3], ah, bh1[2], bh1[3]);
            }
        }
    }

    // epilogue: scatter-add into out[token][h]
    #pragma unroll
    for (int mi = 0; mi < 2; mi++) {
        #pragma unroll
        for (int half = 0; half < 2; half++) {
            int row = wm * 32 + mi * 16 + (lane >> 2) + half * 8;
            if (slot0 + row < cnt) {
                int token = spair[row] >> 1;
                float* orow = out + (size_t)token * H + h0 + wn * 32;
                #pragma unroll
                for (int ni = 0; ni < 4; ni++) {
                    int col = ni * 8 + ((lane & 3) << 1);
                    atomicAdd(&orow[col],     c[mi][ni][half * 2 + 0]);
                    atomicAdd(&orow[col + 1], c[mi][ni][half * 2 + 1]);
                }
            }
        }
    }
}

// ---------------------------------------------------------------------------
extern "C" void kernel_launch(void* const* d_in, const int* in_sizes, int n_in,
                              void* d_out, int out_size) {
    const float* x  = (const float*)d_in[0];
    const float* gw = (const float*)d_in[1];
    const float* Wg = (const float*)d_in[2];
    const float* Wu = (const float*)d_in[3];
    const float* Wd = (const float*)d_in[4];
    float* out = (float*)d_out;

    zero_kernel<<<(T * H + 255) / 256, 256>>>(out);
    router_kernel<<<T, 128>>>(x, gw);
    {
        dim3 grid(T * 2 / BM, I_DIM / BN_GU, E);
        gateup_kernel<<<grid, 256>>>(x, Wg, Wu);
    }
    {
        dim3 grid(T * 2 / BM, H / BN_D, E);
        down_kernel<<<grid, 256>>>(Wd, out);
    }
}